// round 11
// baseline (speedup 1.0000x reference)
#include <cuda_runtime.h>
#include <cuda_fp16.h>
#include <cstdint>

// ---------------- Problem constants ----------------
#define HB   1024          // NUM_BASIC (K)
#define HM   8192          // NUM_MIXED (GEMM M)
#define RR   735           // T*7*7 rows of X (GEMM N, logical)
#define RPAD 768           // padded N
#define NN   57            // output matrix dim
#define OUTN (NN*NN)       // 3249

// ---------------- Scratch (device globals; no allocs allowed) ----------------
__device__ __half g_Xh[RPAD * HB];             // 1.5 MB : X in fp16, rows 735..767 zero
__device__ __half g_Wh[HM * HB];               // 16.7 MB: W in fp16 (RN)
__device__ float  g_Y [(size_t)HM * RPAD];     // 25 MB  : relu(X@W^T + b), [hm][r]

// ---------------- helpers ----------------
__device__ __forceinline__ void cp16(uint32_t s, const void* g) {
    asm volatile("cp.async.cg.shared.global [%0], [%1], 16;" :: "r"(s), "l"(g));
}
__device__ __forceinline__ void mma_f16(float* c, const uint32_t* a, const uint32_t* b) {
    asm volatile(
        "mma.sync.aligned.m16n8k16.row.col.f32.f16.f16.f32 "
        "{%0,%1,%2,%3}, {%4,%5,%6,%7}, {%8,%9}, {%0,%1,%2,%3};"
        : "+f"(c[0]), "+f"(c[1]), "+f"(c[2]), "+f"(c[3])
        : "r"(a[0]), "r"(a[1]), "r"(a[2]), "r"(a[3]), "r"(b[0]), "r"(b[1]));
}
__device__ __forceinline__ void ldsm4(uint32_t* r, uint32_t addr) {
    asm volatile("ldmatrix.sync.aligned.m8n8.x4.shared.b16 {%0,%1,%2,%3}, [%4];"
        : "=r"(r[0]), "=r"(r[1]), "=r"(r[2]), "=r"(r[3]) : "r"(addr));
}

// ---------------- Kernel 1: fused prep (convert W + build X) ----------------
// blocks 0..99      : build_x  (p = b>>1 in 0..49, h-half = b&1)
// blocks 100..2147  : convert_w (512 threads x 8 floats)
__global__ __launch_bounds__(512) void prep_kernel(const float* __restrict__ mat,
                                                   const float* __restrict__ te,
                                                   const float4* __restrict__ W) {
    const int b = blockIdx.x;
    if (b < 100) {
        const int p = b >> 1;
        const int h = (b & 1) * 512 + threadIdx.x;
        if (p == 49) {  // zero padding rows 735..767
            #pragma unroll
            for (int row = RR; row < RPAD; row++) g_Xh[row * HB + h] = __ushort_as_half(0);
            return;
        }
        const int m = p / 7, n = p % 7;
        const float mv = fmaxf(mat[h * 49 + n * 7 + m], 0.f);
        const int rb = m * 7 + n;
        #pragma unroll
        for (int t = 0; t < 15; t++) {
            float s = 1.f + 1.f / (1.f + __expf(-te[h * 15 + t]));
            g_Xh[(t * 49 + rb) * HB + h] = __float2half_rn(s * mv);
        }
    } else {
        const int i = (b - 100) * 512 + threadIdx.x;   // 0 .. HM*HB/8-1
        float4 v0 = W[i * 2];
        float4 v1 = W[i * 2 + 1];
        __half2 h[4];
        h[0] = __floats2half2_rn(v0.x, v0.y);
        h[1] = __floats2half2_rn(v0.z, v0.w);
        h[2] = __floats2half2_rn(v1.x, v1.y);
        h[3] = __floats2half2_rn(v1.z, v1.w);
        *reinterpret_cast<uint4*>(&g_Wh[(size_t)i * 8]) = *reinterpret_cast<uint4*>(h);
    }
}

// ---------------- Kernel 2: fp16 mma.sync GEMM, 128x256 CTA tile, 64x64 warptile ----------------
// C[M=8192(hm)][N=768(r)] = g_Wh @ g_Xh^T ; epilogue: relu(C + b[hm]) -> g_Y
#define KTH 32             // K halfs per smem stage
#define KSH 40             // smem row stride in halfs: 80B rows -> conflict-free LDSM/STS
#define KTILES (HB / KTH)  // 32
#define NSTAGE 3
#define A_H (128 * KSH)                     // A halfs per stage
#define B_H (256 * KSH)                     // B halfs per stage
#define STAGE_T (A_H + B_H)                 // 15360 halfs per stage
#define GEMM_DYN (NSTAGE * STAGE_T * 2)     // 92160 bytes

extern __shared__ __half g_sm[];

__global__ __launch_bounds__(256, 1) void gemm_kernel(const float* __restrict__ bias) {
    const int tid  = threadIdx.x;
    const int lane = tid & 31, warp = tid >> 5;
    const int g  = lane >> 2, t4 = lane & 3;
    const int mb = (warp >> 2) * 64;   // warp grid 2(M) x 4(N)
    const int nb = (warp & 3) * 64;
    const int m0 = blockIdx.y * 128;
    const int n0 = blockIdx.x * 256;

    const int lrow = tid >> 1;            // 0..127
    const int lkc  = (tid & 1) * 2;       // 16B chunk pair

    const uint32_t sBase = (uint32_t)__cvta_generic_to_shared(g_sm);

    const __half* Ag  = g_Wh + (size_t)(m0 + lrow) * HB;
    const __half* Bg0 = g_Xh + (size_t)(n0 + lrow) * HB;
    const __half* Bg1 = g_Xh + (size_t)(n0 + lrow + 128) * HB;

    // ldmatrix per-lane byte offsets relative to stage base
    const int q  = lane >> 3, rr = lane & 7;
    uint32_t aOff[4], bOff[4];
    {
        const int aRow = (q & 1) * 8 + rr, aK = (q >> 1) * 8;
        const int bN   = (q >> 1) * 8 + rr, bK = (q & 1) * 8;
        #pragma unroll
        for (int mt = 0; mt < 4; mt++)
            aOff[mt] = (uint32_t)(((mb + mt * 16 + aRow) * KSH + aK) * 2);
        #pragma unroll
        for (int p = 0; p < 4; p++)
            bOff[p] = (uint32_t)((A_H + (nb + p * 16 + bN) * KSH + bK) * 2);
    }

    float c[4][8][4];
    #pragma unroll
    for (int i = 0; i < 4; i++)
        #pragma unroll
        for (int j = 0; j < 8; j++)
            #pragma unroll
            for (int qq = 0; qq < 4; qq++) c[i][j][qq] = 0.f;

    auto load_stage = [&](int s, int kt) {
        const int k0 = kt * KTH;
        uint32_t sa = sBase + (uint32_t)(s * STAGE_T) * 2u;
        uint32_t sb = sa + (uint32_t)A_H * 2u;
        #pragma unroll
        for (int cch = 0; cch < 2; cch++) {
            int kh = (lkc + cch) * 8;
            uint32_t ro = (uint32_t)(lrow * KSH + kh) * 2u;
            cp16(sa + ro, Ag + k0 + kh);
            cp16(sb + ro, Bg0 + k0 + kh);
            cp16(sb + (uint32_t)(128 * KSH) * 2u + ro, Bg1 + k0 + kh);
        }
        asm volatile("cp.async.commit_group;");
    };

    load_stage(0, 0);
    load_stage(1, 1);

    #pragma unroll 1
    for (int kt = 0; kt < KTILES; kt++) {
        if (kt < KTILES - 2) asm volatile("cp.async.wait_group 1;");
        else                 asm volatile("cp.async.wait_group 0;");
        __syncthreads();
        int cur = kt % NSTAGE;
        if (kt + 2 < KTILES) load_stage((kt + 2) % NSTAGE, kt + 2);

        const uint32_t stBase = sBase + (uint32_t)(cur * STAGE_T) * 2u;
        #pragma unroll
        for (int s16 = 0; s16 < 2; s16++) {
            const uint32_t khB = (uint32_t)(s16 * 16 * 2);
            uint32_t a[4][4], b[4][4];
            #pragma unroll
            for (int mt = 0; mt < 4; mt++)
                ldsm4(a[mt], stBase + aOff[mt] + khB);
            #pragma unroll
            for (int p = 0; p < 4; p++)
                ldsm4(b[p], stBase + bOff[p] + khB);
            #pragma unroll
            for (int mt = 0; mt < 4; mt++)
                #pragma unroll
                for (int nt = 0; nt < 8; nt++)
                    mma_f16(c[mt][nt], a[mt], &b[nt >> 1][(nt & 1) * 2]);
        }
    }

    // epilogue: +bias, relu, store Y[hm][r]
    #pragma unroll
    for (int mt = 0; mt < 4; mt++) {
        #pragma unroll
        for (int qq = 0; qq < 2; qq++) {
            int row = m0 + mb + mt * 16 + g + qq * 8;
            float bv = bias[row];
            #pragma unroll
            for (int nt = 0; nt < 8; nt++) {
                int col = n0 + nb + nt * 8 + t4 * 2;
                float2 v;
                v.x = fmaxf(c[mt][nt][qq * 2 + 0] + bv, 0.f);
                v.y = fmaxf(c[mt][nt][qq * 2 + 1] + bv, 0.f);
                *reinterpret_cast<float2*>(&g_Y[(size_t)row * RPAD + col]) = v;
            }
        }
    }
}

// ---------------- Kernel 3: assemble + degree-normalize ----------------
// mixed[hm,1+row,1+col] = Y[hm, (49-7*(row/7)+col)*7 + row%7]
// row 0 / col 0: identity entries at multiples of 7. d = clip(rowsum,1)^-0.5.
__global__ __launch_bounds__(228) void assemble_kernel(float* __restrict__ out) {
    __shared__ float sy[RR + 1];
    __shared__ float sd[NN];
    __shared__ float psum[4][NN + 1];
    __shared__ int   rbase[NN];

    const int tid = threadIdx.x;
    const int jc  = tid % 57;
    const int ty  = tid / 57;
    const int hm  = blockIdx.x;
    const float* yrow = g_Y + (size_t)hm * RPAD;

    for (int r = tid; r < RR; r += 228) sy[r] = yrow[r];
    if (tid > 0 && tid < NN) {
        int row = tid - 1, j = row / 7, n = row % 7;
        rbase[tid] = (49 - 7 * j) * 7 + n;
    }
    __syncthreads();

    {
        float acc = 0.f;
        if (jc > 0) {
            int base = rbase[jc] + ty * 14 * 7;
            #pragma unroll
            for (int cc = 0; cc < 14; cc++) acc += sy[base + cc * 7];
        }
        psum[ty][jc] = acc;
    }
    __syncthreads();

    if (tid < NN) {
        float s;
        if (tid == 0) s = 9.f;
        else {
            s = psum[0][tid] + psum[1][tid] + psum[2][tid] + psum[3][tid];
            if ((tid % 7) == 0) s += 1.f;
        }
        sd[tid] = (s <= 1.f) ? 1.f : rsqrtf(s);
    }
    __syncthreads();

    const size_t ob  = (size_t)hm * OUTN;
    const float  sdj = sd[jc];
    const bool   jc7 = (jc % 7) == 0;
    const int    gcol = (jc - 1) * 7;

    #pragma unroll
    for (int it = 0; it < 15; it++) {
        int i = ty + it * 4;
        if (i >= NN) break;
        float v;
        if (i == 0)        v = jc7 ? sd[0] * sdj : 0.f;
        else if (jc == 0)  v = ((i % 7) == 0) ? sd[i] * sd[0] : 0.f;
        else               v = sd[i] * sdj * sy[rbase[i] + gcol];
        out[ob + i * NN + jc] = v;
    }
}

// ---------------- launch ----------------
extern "C" void kernel_launch(void* const* d_in, const int* in_sizes, int n_in,
                              void* d_out, int out_size) {
    const float* mat = (const float*)d_in[0];
    const float* te  = (const float*)d_in[1];
    const float* W   = (const float*)d_in[2];
    const float* b   = (const float*)d_in[3];
    float* out = (float*)d_out;

    cudaFuncSetAttribute(gemm_kernel, cudaFuncAttributeMaxDynamicSharedMemorySize, GEMM_DYN);

    prep_kernel<<<2148, 512>>>(mat, te, (const float4*)W);
    gemm_kernel<<<dim3(3, 64), 256, GEMM_DYN>>>(b);
    assemble_kernel<<<HM, 228>>>(out);
}

// round 13
// speedup vs baseline: 1.2794x; 1.2794x over previous
#include <cuda_runtime.h>
#include <cuda_fp16.h>
#include <cstdint>

// ---------------- Problem constants ----------------
#define HB   1024          // NUM_BASIC (K)
#define HM   8192          // NUM_MIXED (GEMM M)
#define RR   735           // T*7*7 rows of X (GEMM N, logical)
#define RPAD 768           // padded N
#define NN   57            // output matrix dim
#define OUTN (NN*NN)       // 3249

// ---------------- Scratch (device globals; no allocs allowed) ----------------
__device__ __half g_Xh[RPAD * HB];             // 1.5 MB : X in fp16, rows 735..767 zero
__device__ __half g_Wh[HM * HB];               // 16.7 MB: W in fp16 (RN)
__device__ float  g_Y [(size_t)HM * RPAD];     // 25 MB  : relu(X@W^T + b), [hm][r]

// ---------------- helpers ----------------
__device__ __forceinline__ void cp16(uint32_t s, const void* g) {
    asm volatile("cp.async.cg.shared.global [%0], [%1], 16;" :: "r"(s), "l"(g));
}
__device__ __forceinline__ void mma_f16(float* c, const uint32_t* a, const uint32_t* b) {
    asm volatile(
        "mma.sync.aligned.m16n8k16.row.col.f32.f16.f16.f32 "
        "{%0,%1,%2,%3}, {%4,%5,%6,%7}, {%8,%9}, {%0,%1,%2,%3};"
        : "+f"(c[0]), "+f"(c[1]), "+f"(c[2]), "+f"(c[3])
        : "r"(a[0]), "r"(a[1]), "r"(a[2]), "r"(a[3]), "r"(b[0]), "r"(b[1]));
}
__device__ __forceinline__ void ldsm4(uint32_t* r, uint32_t addr) {
    asm volatile("ldmatrix.sync.aligned.m8n8.x4.shared.b16 {%0,%1,%2,%3}, [%4];"
        : "=r"(r[0]), "=r"(r[1]), "=r"(r[2]), "=r"(r[3]) : "r"(addr));
}

// ---------------- Kernel 1: fused prep (convert W + build X) ----------------
// blocks 0..99      : build_x  (p = b>>1 in 0..49, h-half = b&1)
// blocks 100..2147  : convert_w (512 threads x 8 floats)
__global__ __launch_bounds__(512) void prep_kernel(const float* __restrict__ mat,
                                                   const float* __restrict__ te,
                                                   const float4* __restrict__ W) {
    const int b = blockIdx.x;
    if (b < 100) {
        const int p = b >> 1;
        const int h = (b & 1) * 512 + threadIdx.x;
        if (p == 49) {  // zero padding rows 735..767
            #pragma unroll
            for (int row = RR; row < RPAD; row++) g_Xh[row * HB + h] = __ushort_as_half(0);
            return;
        }
        const int m = p / 7, n = p % 7;
        const float mv = fmaxf(mat[h * 49 + n * 7 + m], 0.f);
        const int rb = m * 7 + n;
        #pragma unroll
        for (int t = 0; t < 15; t++) {
            float s = 1.f + 1.f / (1.f + __expf(-te[h * 15 + t]));
            g_Xh[(t * 49 + rb) * HB + h] = __float2half_rn(s * mv);
        }
    } else {
        const int i = (b - 100) * 512 + threadIdx.x;   // 0 .. HM*HB/8-1
        float4 v0 = W[i * 2];
        float4 v1 = W[i * 2 + 1];
        __half2 h[4];
        h[0] = __floats2half2_rn(v0.x, v0.y);
        h[1] = __floats2half2_rn(v0.z, v0.w);
        h[2] = __floats2half2_rn(v1.x, v1.y);
        h[3] = __floats2half2_rn(v1.z, v1.w);
        *reinterpret_cast<uint4*>(&g_Wh[(size_t)i * 8]) = *reinterpret_cast<uint4*>(h);
    }
}

// ---------------- Kernel 2: fp16 mma.sync GEMM, 128x96 CTA tile, 32x48 warptile ----------------
// C[M=8192(hm)][N=768(r)] = g_Wh @ g_Xh^T ; epilogue: relu(C + b[hm]) -> g_Y
// Grid 8x64 = 512 CTAs @ 2/SM -> 86.5% wave utilization (vs 65% at 6x64).
#define NT   96            // N tile
#define KTH  32            // K halfs per smem stage
#define KSH  40            // smem row stride in halfs: 80B rows -> conflict-free LDSM/STS
#define KTILES (HB / KTH)  // 32
#define NSTAGE 3
#define A_H (128 * KSH)                     // A halfs per stage (5120)
#define B_H (NT * KSH)                      // B halfs per stage (3840)
#define STAGE_T (A_H + B_H)                 // 8960 halfs per stage
#define GEMM_DYN (NSTAGE * STAGE_T * 2)     // 53760 bytes
#define CHUNKS ((128 + NT) * 4)             // 16B chunks per stage = 896

extern __shared__ __half g_sm[];

__global__ __launch_bounds__(256, 2) void gemm_kernel(const float* __restrict__ bias) {
    const int tid  = threadIdx.x;
    const int lane = tid & 31, warp = tid >> 5;
    const int g  = lane >> 2, t4 = lane & 3;
    const int mb = (warp >> 1) * 32;   // warp grid 4(M) x 2(N)
    const int nb = (warp & 1) * 48;
    const int m0 = blockIdx.y * 128;
    const int n0 = blockIdx.x * NT;

    const uint32_t sBase = (uint32_t)__cvta_generic_to_shared(g_sm);

    const __half* Ag = g_Wh + (size_t)m0 * HB;
    const __half* Bg = g_Xh + (size_t)n0 * HB;

    // ldmatrix per-lane byte offsets relative to stage base
    const int q  = lane >> 3, rr = lane & 7;
    uint32_t aOff[2], bOff[3];
    {
        const int aRow = (q & 1) * 8 + rr, aK = (q >> 1) * 8;
        const int bN   = (q >> 1) * 8 + rr, bK = (q & 1) * 8;
        #pragma unroll
        for (int mt = 0; mt < 2; mt++)
            aOff[mt] = (uint32_t)(((mb + mt * 16 + aRow) * KSH + aK) * 2);
        #pragma unroll
        for (int p = 0; p < 3; p++)
            bOff[p] = (uint32_t)((A_H + (nb + p * 16 + bN) * KSH + bK) * 2);
    }

    float c[2][6][4];
    #pragma unroll
    for (int i = 0; i < 2; i++)
        #pragma unroll
        for (int j = 0; j < 6; j++)
            #pragma unroll
            for (int qq = 0; qq < 4; qq++) c[i][j][qq] = 0.f;

    // generic chunked loader: chunk = (row, kc); rows 0..127 = A, 128..223 = B
    auto load_stage = [&](int s, int kt) {
        const int k0 = kt * KTH;
        const uint32_t stg = sBase + (uint32_t)(s * STAGE_T) * 2u;
        #pragma unroll
        for (int it = 0; it < 4; it++) {
            int ch = tid + it * 256;
            if (it < 3 || ch < CHUNKS) {
                int row = ch >> 2, kc = (ch & 3) * 8;
                const __half* src;
                uint32_t dst;
                if (row < 128) {
                    src = Ag + (size_t)row * HB + k0 + kc;
                    dst = stg + (uint32_t)(row * KSH + kc) * 2u;
                } else {
                    src = Bg + (size_t)(row - 128) * HB + k0 + kc;
                    dst = stg + (uint32_t)(A_H + (row - 128) * KSH + kc) * 2u;
                }
                cp16(dst, src);
            }
        }
        asm volatile("cp.async.commit_group;");
    };

    load_stage(0, 0);
    load_stage(1, 1);

    #pragma unroll 1
    for (int kt = 0; kt < KTILES; kt++) {
        if (kt < KTILES - 2) asm volatile("cp.async.wait_group 1;");
        else                 asm volatile("cp.async.wait_group 0;");
        __syncthreads();
        int cur = kt % NSTAGE;
        if (kt + 2 < KTILES) load_stage((kt + 2) % NSTAGE, kt + 2);

        const uint32_t stBase = sBase + (uint32_t)(cur * STAGE_T) * 2u;
        #pragma unroll
        for (int s16 = 0; s16 < 2; s16++) {
            const uint32_t khB = (uint32_t)(s16 * 16 * 2);
            uint32_t a[2][4], b[3][4];
            ldsm4(a[0], stBase + aOff[0] + khB);
            ldsm4(a[1], stBase + aOff[1] + khB);
            #pragma unroll
            for (int p = 0; p < 3; p++)
                ldsm4(b[p], stBase + bOff[p] + khB);
            #pragma unroll
            for (int mt = 0; mt < 2; mt++)
                #pragma unroll
                for (int nt = 0; nt < 6; nt++)
                    mma_f16(c[mt][nt], a[mt], &b[nt >> 1][(nt & 1) * 2]);
        }
    }

    // epilogue: +bias, relu, store Y[hm][r]
    #pragma unroll
    for (int mt = 0; mt < 2; mt++) {
        #pragma unroll
        for (int qq = 0; qq < 2; qq++) {
            int row = m0 + mb + mt * 16 + g + qq * 8;
            float bv = bias[row];
            #pragma unroll
            for (int nt = 0; nt < 6; nt++) {
                int col = n0 + nb + nt * 8 + t4 * 2;
                float2 v;
                v.x = fmaxf(c[mt][nt][qq * 2 + 0] + bv, 0.f);
                v.y = fmaxf(c[mt][nt][qq * 2 + 1] + bv, 0.f);
                *reinterpret_cast<float2*>(&g_Y[(size_t)row * RPAD + col]) = v;
            }
        }
    }
}

// ---------------- Kernel 3: assemble + degree-normalize ----------------
// mixed[hm,1+row,1+col] = Y[hm, (49-7*(row/7)+col)*7 + row%7]
// row 0 / col 0: identity entries at multiples of 7. d = clip(rowsum,1)^-0.5.
__global__ __launch_bounds__(228) void assemble_kernel(float* __restrict__ out) {
    __shared__ float sy[RR + 1];
    __shared__ float sd[NN];
    __shared__ float psum[4][NN + 1];
    __shared__ int   rbase[NN];

    const int tid = threadIdx.x;
    const int jc  = tid % 57;
    const int ty  = tid / 57;
    const int hm  = blockIdx.x;
    const float* yrow = g_Y + (size_t)hm * RPAD;

    for (int r = tid; r < RR; r += 228) sy[r] = yrow[r];
    if (tid > 0 && tid < NN) {
        int row = tid - 1, j = row / 7, n = row % 7;
        rbase[tid] = (49 - 7 * j) * 7 + n;
    }
    __syncthreads();

    {
        float acc = 0.f;
        if (jc > 0) {
            int base = rbase[jc] + ty * 14 * 7;
            #pragma unroll
            for (int cc = 0; cc < 14; cc++) acc += sy[base + cc * 7];
        }
        psum[ty][jc] = acc;
    }
    __syncthreads();

    if (tid < NN) {
        float s;
        if (tid == 0) s = 9.f;
        else {
            s = psum[0][tid] + psum[1][tid] + psum[2][tid] + psum[3][tid];
            if ((tid % 7) == 0) s += 1.f;
        }
        sd[tid] = (s <= 1.f) ? 1.f : rsqrtf(s);
    }
    __syncthreads();

    const size_t ob  = (size_t)hm * OUTN;
    const float  sdj = sd[jc];
    const bool   jc7 = (jc % 7) == 0;
    const int    gcol = (jc - 1) * 7;

    #pragma unroll
    for (int it = 0; it < 15; it++) {
        int i = ty + it * 4;
        if (i >= NN) break;
        float v;
        if (i == 0)        v = jc7 ? sd[0] * sdj : 0.f;
        else if (jc == 0)  v = ((i % 7) == 0) ? sd[i] * sd[0] : 0.f;
        else               v = sd[i] * sdj * sy[rbase[i] + gcol];
        out[ob + i * NN + jc] = v;
    }
}

// ---------------- launch ----------------
extern "C" void kernel_launch(void* const* d_in, const int* in_sizes, int n_in,
                              void* d_out, int out_size) {
    const float* mat = (const float*)d_in[0];
    const float* te  = (const float*)d_in[1];
    const float* W   = (const float*)d_in[2];
    const float* b   = (const float*)d_in[3];
    float* out = (float*)d_out;

    cudaFuncSetAttribute(gemm_kernel, cudaFuncAttributeMaxDynamicSharedMemorySize, GEMM_DYN);

    prep_kernel<<<2148, 512>>>(mat, te, (const float4*)W);
    gemm_kernel<<<dim3(8, 64), 256, GEMM_DYN>>>(b);
    assemble_kernel<<<HM, 228>>>(out);
}